// round 13
// baseline (speedup 1.0000x reference)
#include <cuda_runtime.h>
#include <cstdint>

#define NTRIP 55
#define DTOT  404480
#define EPSV  1e-6f
#define NKB   395
#define KSPAN 1024
#define NCH   32

// -------- compile-time triple tables (sorted by l3, stable in TRIPLES order) --------
__constant__ int c_l1[NTRIP] = {
    0,1,2,3,4, 0,1,1,2,2,3,3,4, 0,1,1,1,2,2,2,3,3,4, 0,1,1,1,2,2,2,3,3,4,
    0,1,1,2,2,2,3,3,4, 1,2,2,3,3,4, 2,3,3,4, 3,4, 4};
__constant__ int c_l2[NTRIP] = {
    0,1,2,3,4, 1,1,2,2,3,3,4,4, 2,1,2,3,2,3,4,3,4,4, 3,2,3,4,2,3,4,3,4,4,
    4,3,4,2,3,4,3,4,4, 4,3,4,3,4,4, 4,3,4,4, 4,4, 4};
__constant__ int c_l3a[NTRIP] = {
    0,0,0,0,0, 1,1,1,1,1,1,1,1, 2,2,2,2,2,2,2,2,2,2, 3,3,3,3,3,3,3,3,3,3,
    4,4,4,4,4,4,4,4,4, 5,5,5,5,5,5, 6,6,6,6, 7,7, 8};
__constant__ int c_widx[NTRIP] = {
    0,5,17,32,46, 1,6,8,18,22,33,39,47, 2,7,9,11,19,23,27,34,40,48,
    3,10,12,14,20,24,28,35,41,49, 4,13,15,21,25,29,36,42,50,
    16,26,30,37,43,51, 31,38,44,52, 45,53, 54};
__constant__ int c_based[NTRIP] = {
    0,1024,2048,3072,4096,
    5120,8192,11264,14336,17408,20480,23552,26624,
    29696,34816,39936,45056,50176,55296,60416,65536,70656,75776,
    80896,88064,95232,102400,109568,116736,123904,131072,138240,145408,
    152576,161792,171008,180224,189440,198656,207872,217088,226304,
    235520,246784,258048,269312,280576,291840,
    303104,316416,329728,343040,
    356352,371712,
    387072};

__device__ float d_blksum[NTRIP * 64];   // per-(tr,b) sum of z1^2 (overwritten each replay)
__device__ float d_blk0[5 * 64];         // per-(tr,b) sum of z1 for l3=0 triples
__device__ float d_z[64LL * DTOT];
__device__ float d_csq[DTOT];
__device__ float d_csum[DTOT];
__device__ float d_g[DTOT];
__device__ float d_m[5120];
__device__ float d_part[(long)NKB * 8192];

__device__ __forceinline__ float tf32r(float x) {
    asm("cvt.rna.tf32.f32 %0, %0;" : "+f"(x));
    return x;
}

// LN+power affine per (b, l3) from per-block sums (no atomics, no zeroing)
__device__ __forceinline__ void computeAD(int b, int l3v, float& A, float& D) {
    const int tro[10] = {0, 5, 13, 23, 33, 42, 48, 52, 54, 55};
    float power = 0.f;
    #pragma unroll
    for (int tr = 0; tr < NTRIP; tr++) power += d_blksum[tr*64 + b];
    float s = 0.f;
    for (int tr = tro[l3v]; tr < tro[l3v+1]; tr++) s += d_blksum[tr*64 + b];
    float scale = rsqrtf(power / (float)DTOT + EPSV);
    float cnt = (float)((tro[l3v+1] - tro[l3v]) * 1024 * (2*l3v + 1));
    float ms = scale * scale * s / cnt;
    if (l3v == 0) {
        float s0 = 0.f;
        #pragma unroll
        for (int tr = 0; tr < 5; tr++) s0 += d_blk0[tr*64 + b];
        float mu = scale * s0 / cnt;
        float c  = rsqrtf(ms - mu*mu + EPSV);
        A = scale * c; D = -mu * c;
    } else {
        A = scale * rsqrtf(ms + EPSV); D = 0.f;
    }
}

__device__ __forceinline__ int regionOf(long d) {
    if (d < 5120)   return 0;
    if (d < 29696)  return 1;
    if (d < 80896)  return 2;
    if (d < 152576) return 3;
    if (d < 235520) return 4;
    if (d < 303104) return 5;
    if (d < 356352) return 6;
    if (d < 387072) return 7;
    return 8;
}

// ------------- triple products (y computed in-block) + row-norm + LN stats -------------
template <int K3>
__device__ __forceinline__ void trip_body(int tr, int b, const float* const* xs,
                                          const float* __restrict__ Wlin,
                                          const float* __restrict__ bias0,
                                          const float* __restrict__ w3j,
                                          float* sx1, float* sx2,
                                          float* sy1, float* sy2, float* sw, float* su,
                                          float* rw1, float* rw2) {
    constexpr int K3A = (K3 + 3) & ~3;
    constexpr int NV  = K3A / 4;
    const int l1 = c_l1[tr], l2 = c_l2[tr];
    const int m1 = 2*l1 + 1, n2 = 2*l2 + 1;
    int t = threadIdx.x, lane = t & 31, w = t >> 5;

    // load x tiles + w3j
    const float* xp1 = xs[l1] + (long)b * 32 * m1;
    for (int e = t; e < 32*m1; e += 256) sx1[e] = xp1[e];
    const float* xp2 = xs[l2] + (long)b * 32 * n2;
    for (int e = t; e < 32*n2; e += 256) sx2[e] = xp2[e];
    const float* wp = w3j + (long)c_widx[tr] * 9 * 9 * 17;
    for (int e = t; e < m1*n2*K3; e += 256) {
        int m = e / (n2*K3), r = e % (n2*K3), nn = r / K3, k = r % K3;
        sw[e] = wp[m*153 + nn*17 + k];
    }
    __syncthreads();
    // y = Wlin @ x (+bias0 on l==0)
    for (int e = t; e < 32*m1; e += 256) {
        int i = e / m1, m = e % m1;
        float acc = (l1 == 0) ? bias0[i] : 0.f;
        const float* wr = Wlin + l1*1024 + i*32;
        #pragma unroll 8
        for (int cc = 0; cc < 32; cc++) acc += wr[cc] * sx1[cc*m1 + m];
        sy1[e] = acc;
    }
    for (int e = t; e < 32*n2; e += 256) {
        int j = e / n2, n = e % n2;
        float acc = (l2 == 0) ? bias0[j] : 0.f;
        const float* wr = Wlin + l2*1024 + j*32;
        #pragma unroll 8
        for (int cc = 0; cc < 32; cc++) acc += wr[cc] * sx2[cc*n2 + n];
        sy2[e] = acc;
    }
    __syncthreads();
    // u[i,n,k] = sum_m y1[i,m] w[m,n,k]
    for (int e = t; e < 32*n2*K3; e += 256) {
        int i = e / (n2*K3), r = e % (n2*K3), nn = r / K3, k = r % K3;
        float a = 0.f;
        for (int m = 0; m < m1; m++) a += sy1[i*m1 + m] * sw[(m*n2 + nn)*K3 + k];
        su[(i*n2 + nn)*K3A + k] = a;
    }
    __syncthreads();

    float lsq = 0.f, ls0 = 0.f;
    long zbase = (long)b * DTOT + c_based[tr];
    for (int p = t; p < 1024; p += 256) {
        int j = p & 31;         // = lane
        int iw = p >> 5;        // warp-constant -> su reads broadcast
        float4 acc4[NV];
        #pragma unroll
        for (int q = 0; q < NV; q++) acc4[q] = make_float4(0.f, 0.f, 0.f, 0.f);
        const float* y2p = &sy2[j*n2];
        for (int n = 0; n < n2; n++) {
            float yn = y2p[n];
            const float4* up = (const float4*)&su[(iw*n2 + n)*K3A];
            #pragma unroll
            for (int q = 0; q < NV; q++) {
                float4 u4 = up[q];
                acc4[q].x += yn*u4.x; acc4[q].y += yn*u4.y;
                acc4[q].z += yn*u4.z; acc4[q].w += yn*u4.w;
            }
        }
        float S = 0.f;
        #pragma unroll
        for (int q = 0; q < NV; q++) {
            if (4*q + 0 < K3) S += acc4[q].x*acc4[q].x;
            if (4*q + 1 < K3) S += acc4[q].y*acc4[q].y;
            if (4*q + 2 < K3) S += acc4[q].z*acc4[q].z;
            if (4*q + 3 < K3) S += acc4[q].w*acc4[q].w;
        }
        float inv = rsqrtf(S + EPSV);
        float* zp = &d_z[zbase + (long)p * K3];
        #pragma unroll
        for (int q = 0; q < NV; q++) {
            if (4*q + 0 < K3) zp[4*q + 0] = acc4[q].x * inv;
            if (4*q + 1 < K3) zp[4*q + 1] = acc4[q].y * inv;
            if (4*q + 2 < K3) zp[4*q + 2] = acc4[q].z * inv;
            if (4*q + 3 < K3) zp[4*q + 3] = acc4[q].w * inv;
        }
        lsq += S * inv * inv;
        if (K3 == 1) ls0 += acc4[0].x * inv;
    }
    #pragma unroll
    for (int o = 16; o > 0; o >>= 1) {
        lsq += __shfl_xor_sync(0xFFFFFFFFu, lsq, o);
        if (K3 == 1) ls0 += __shfl_xor_sync(0xFFFFFFFFu, ls0, o);
    }
    if (lane == 0) { rw1[w] = lsq; rw2[w] = ls0; }
    __syncthreads();
    if (t == 0) {
        float s1 = 0.f, s2 = 0.f;
        #pragma unroll
        for (int q = 0; q < 8; q++) { s1 += rw1[q]; s2 += rw2[q]; }
        d_blksum[tr*64 + b] = s1;
        if (K3 == 1) d_blk0[tr*64 + b] = s2;
    }
}

__global__ void __launch_bounds__(256) k_trip_all(
        const float* __restrict__ x0, const float* __restrict__ x1,
        const float* __restrict__ x2, const float* __restrict__ x3,
        const float* __restrict__ x4, const float* __restrict__ Wlin,
        const float* __restrict__ bias0, const float* __restrict__ w3j) {
    __shared__ float sx1[288], sx2[288], sy1[288], sy2[288], sw[1377];
    __shared__ __align__(16) float su[5760];
    __shared__ float rw1[8], rw2[8];
    int tr = blockIdx.x, b = blockIdx.y;
    const float* xs[5] = {x0, x1, x2, x3, x4};
    switch (c_l3a[tr]) {
        case 0: trip_body<1> (tr, b, xs, Wlin, bias0, w3j, sx1, sx2, sy1, sy2, sw, su, rw1, rw2); break;
        case 1: trip_body<3> (tr, b, xs, Wlin, bias0, w3j, sx1, sx2, sy1, sy2, sw, su, rw1, rw2); break;
        case 2: trip_body<5> (tr, b, xs, Wlin, bias0, w3j, sx1, sx2, sy1, sy2, sw, su, rw1, rw2); break;
        case 3: trip_body<7> (tr, b, xs, Wlin, bias0, w3j, sx1, sx2, sy1, sy2, sw, su, rw1, rw2); break;
        case 4: trip_body<9> (tr, b, xs, Wlin, bias0, w3j, sx1, sx2, sy1, sy2, sw, su, rw1, rw2); break;
        case 5: trip_body<11>(tr, b, xs, Wlin, bias0, w3j, sx1, sx2, sy1, sy2, sw, su, rw1, rw2); break;
        case 6: trip_body<13>(tr, b, xs, Wlin, bias0, w3j, sx1, sx2, sy1, sy2, sw, su, rw1, rw2); break;
        case 7: trip_body<15>(tr, b, xs, Wlin, bias0, w3j, sx1, sx2, sy1, sy2, sw, su, rw1, rw2); break;
        case 8: trip_body<17>(tr, b, xs, Wlin, bias0, w3j, sx1, sx2, sy1, sy2, sw, su, rw1, rw2); break;
    }
}

// ------------- BN column stats: stream z once, per-d csq/csum -------------
__global__ void __launch_bounds__(128) k_bncol() {
    int bid = blockIdx.x, t = threadIdx.x;
    long d0 = (long)bid * 512;
    int l3v = regionOf(d0);
    __shared__ float sA[64], sD[64];
    if (t < 64) computeAD(t, l3v, sA[t], sD[t]);
    __syncthreads();
    long dd = d0 + (long)t * 4;
    float4 sq = make_float4(0.f,0.f,0.f,0.f), sm = make_float4(0.f,0.f,0.f,0.f);
    #pragma unroll 4
    for (int b = 0; b < 64; b++) {
        float4 z4 = *(const float4*)&d_z[(long)b*DTOT + dd];
        float a = sA[b], dv = sD[b];
        float vx = a*z4.x + dv, vy = a*z4.y + dv, vz = a*z4.z + dv, vw = a*z4.w + dv;
        sq.x += vx*vx; sq.y += vy*vy; sq.z += vz*vz; sq.w += vw*vw;
        sm.x += vx;    sm.y += vy;    sm.z += vz;    sm.w += vw;
    }
    *(float4*)&d_csq[dd]  = sq;
    *(float4*)&d_csum[dd] = sm;
}

// ------------- BN reduce: per-(tr,i,j) gain (and mean for l3=0) -------------
__global__ void k_bnred() {
    int id = blockIdx.x, tr = id >> 5, i = id & 31;
    int j = threadIdx.x;
    int l3v = c_l3a[tr], k3 = 2*l3v + 1;
    long base = (long)c_based[tr] + (long)(i*32 + j) * k3;
    float sq = 0.f, sm = 0.f;
    for (int k = 0; k < k3; k++) { sq += d_csq[base + k]; sm += d_csum[base + k]; }
    float gj, mj = 0.f;
    if (l3v == 0) {
        float m = sm * (1.f/64.f);
        gj = rsqrtf(sq*(1.f/64.f) - m*m + EPSV); mj = m;
    } else {
        gj = rsqrtf(sq / (64.f * (float)k3) + EPSV);
    }
    for (int k = 0; k < k3; k++) {
        d_g[base + k] = gj;
        if (l3v == 0) d_m[base + k] = mj;
    }
}

// ------------- split-K GEMM via mma.sync tf32, BN affine fused, depth-2 W prefetch -------------
__global__ void __launch_bounds__(256, 2) k_gemm_mma(const float* __restrict__ W) {
    __shared__ float As[128][36];
    __shared__ float Bs[64][36];
    __shared__ float sA[64], sD[64];
    int t = threadIdx.x;
    int w = t >> 5, lane = t & 31, gid = lane >> 2, tid4 = lane & 3;
    long kbase = (long)blockIdx.x * KSPAN;
    int l3v = regionOf(kbase);
    bool hasm = (l3v == 0);

    if (t < 64) computeAD(t, l3v, sA[t], sD[t]);
    __syncthreads();

    float c[8][4];
    #pragma unroll
    for (int nt = 0; nt < 8; nt++)
        #pragma unroll
        for (int q = 0; q < 4; q++) c[nt][q] = 0.f;

    float4 av[2][4], bv[2], gv[2], mv[2];
    // prologue: W chunks 0,1 + B chunk 0
    #pragma unroll
    for (int s = 0; s < 2; s++)
        #pragma unroll
        for (int i = 0; i < 4; i++) {
            int id = t + i*256, r = id >> 3, cc = (id & 7) * 4;
            av[s][i] = *(const float4*)(W + (long)r*DTOT + kbase + s*32 + cc);
        }
    #pragma unroll
    for (int i = 0; i < 2; i++) {
        int id = t + i*256, r = id >> 3, cc = (id & 7) * 4;
        bv[i] = *(const float4*)(d_z + (long)r*DTOT + kbase + cc);
        gv[i] = *(const float4*)(d_g + kbase + cc);
        mv[i] = hasm ? *(const float4*)(d_m + kbase + cc) : make_float4(0.f,0.f,0.f,0.f);
    }

    for (int ch = 0; ch < NCH; ch++) {
        int s = ch & 1;
        #pragma unroll
        for (int i = 0; i < 4; i++) {
            int id = t + i*256, r = id >> 3, cc = (id & 7) * 4;
            float4 v = av[s][i];
            v.x = tf32r(v.x); v.y = tf32r(v.y); v.z = tf32r(v.z); v.w = tf32r(v.w);
            *(float4*)&As[r][cc] = v;
        }
        #pragma unroll
        for (int i = 0; i < 2; i++) {
            int id = t + i*256, r = id >> 3, cc = (id & 7) * 4;
            float a = sA[r], dd = sD[r];
            float4 v;
            v.x = tf32r(gv[i].x * (a*bv[i].x + dd - mv[i].x));
            v.y = tf32r(gv[i].y * (a*bv[i].y + dd - mv[i].y));
            v.z = tf32r(gv[i].z * (a*bv[i].z + dd - mv[i].z));
            v.w = tf32r(gv[i].w * (a*bv[i].w + dd - mv[i].w));
            *(float4*)&Bs[r][cc] = v;
        }
        __syncthreads();
        // prefetch W chunk ch+2 into the set just consumed; B chunk ch+1
        if (ch + 2 < NCH) {
            long kg = kbase + (ch + 2) * 32;
            #pragma unroll
            for (int i = 0; i < 4; i++) {
                int id = t + i*256, r = id >> 3, cc = (id & 7) * 4;
                av[s][i] = *(const float4*)(W + (long)r*DTOT + kg + cc);
            }
        }
        if (ch + 1 < NCH) {
            long kg = kbase + (ch + 1) * 32;
            #pragma unroll
            for (int i = 0; i < 2; i++) {
                int id = t + i*256, r = id >> 3, cc = (id & 7) * 4;
                bv[i] = *(const float4*)(d_z + (long)r*DTOT + kg + cc);
                gv[i] = *(const float4*)(d_g + kg + cc);
                mv[i] = hasm ? *(const float4*)(d_m + kg + cc) : make_float4(0.f,0.f,0.f,0.f);
            }
        }
        #pragma unroll
        for (int ks = 0; ks < 4; ks++) {
            int k0 = ks * 8;
            int ar = w*16 + gid;
            unsigned a0 = __float_as_uint(As[ar][k0 + tid4]);
            unsigned a1 = __float_as_uint(As[ar + 8][k0 + tid4]);
            unsigned a2 = __float_as_uint(As[ar][k0 + tid4 + 4]);
            unsigned a3 = __float_as_uint(As[ar + 8][k0 + tid4 + 4]);
            #pragma unroll
            for (int nt = 0; nt < 8; nt++) {
                unsigned b0 = __float_as_uint(Bs[nt*8 + gid][k0 + tid4]);
                unsigned b1 = __float_as_uint(Bs[nt*8 + gid][k0 + tid4 + 4]);
                asm volatile(
                    "mma.sync.aligned.m16n8k8.row.col.f32.tf32.tf32.f32 "
                    "{%0,%1,%2,%3}, {%4,%5,%6,%7}, {%8,%9}, {%0,%1,%2,%3};"
                    : "+f"(c[nt][0]), "+f"(c[nt][1]), "+f"(c[nt][2]), "+f"(c[nt][3])
                    : "r"(a0), "r"(a1), "r"(a2), "r"(a3), "r"(b0), "r"(b1));
            }
        }
        __syncthreads();
    }

    long pb = (long)blockIdx.x * 8192;
    int j0 = w*16 + gid, n0 = tid4 * 2;
    #pragma unroll
    for (int nt = 0; nt < 8; nt++) {
        int n = nt*8 + n0;
        *(float2*)&d_part[pb + (long)j0*64 + n]       = make_float2(c[nt][0], c[nt][1]);
        *(float2*)&d_part[pb + (long)(j0 + 8)*64 + n] = make_float2(c[nt][2], c[nt][3]);
    }
}

// ------------- reduce partials + bias, split (mu, logvar) -------------
__global__ void k_fin(const float* __restrict__ bfc, float* __restrict__ out) {
    int e = blockIdx.x * blockDim.x + threadIdx.x;
    if (e >= 8192) return;
    float s = 0.f;
    #pragma unroll 8
    for (int blk = 0; blk < NKB; blk++) s += d_part[(long)blk * 8192 + e];
    int j = e >> 6, b = e & 63;
    out[(j >> 6) * 4096 + b*64 + (j & 63)] = s + bfc[j];
}

extern "C" void kernel_launch(void* const* d_in, const int* in_sizes, int n_in,
                              void* d_out, int out_size) {
    const float* x0    = (const float*)d_in[0];
    const float* x1    = (const float*)d_in[1];
    const float* x2    = (const float*)d_in[2];
    const float* x3    = (const float*)d_in[3];
    const float* x4    = (const float*)d_in[4];
    const float* Wlin  = (const float*)d_in[5];
    const float* bias0 = (const float*)d_in[6];
    const float* w3j   = (const float*)d_in[7];
    const float* Wfc   = (const float*)d_in[8];
    const float* bfc   = (const float*)d_in[9];
    float* out = (float*)d_out;

    k_trip_all<<<dim3(NTRIP, 64), 256>>>(x0, x1, x2, x3, x4, Wlin, bias0, w3j);
    k_bncol<<<DTOT/512, 128>>>();
    k_bnred<<<NTRIP*32, 32>>>();
    k_gemm_mma<<<NKB, 256>>>(Wfc);
    k_fin<<<32, 256>>>(bfc, out);
}

// round 15
// speedup vs baseline: 1.3251x; 1.3251x over previous
#include <cuda_runtime.h>
#include <cstdint>

#define NTRIP 55
#define DTOT  404480
#define EPSV  1e-6f
#define NKB   395
#define KSPAN 1024
#define NCH   32

// -------- compile-time triple tables (sorted by l3, stable in TRIPLES order) --------
__constant__ int c_l1[NTRIP] = {
    0,1,2,3,4, 0,1,1,2,2,3,3,4, 0,1,1,1,2,2,2,3,3,4, 0,1,1,1,2,2,2,3,3,4,
    0,1,1,2,2,2,3,3,4, 1,2,2,3,3,4, 2,3,3,4, 3,4, 4};
__constant__ int c_l2[NTRIP] = {
    0,1,2,3,4, 1,1,2,2,3,3,4,4, 2,1,2,3,2,3,4,3,4,4, 3,2,3,4,2,3,4,3,4,4,
    4,3,4,2,3,4,3,4,4, 4,3,4,3,4,4, 4,3,4,4, 4,4, 4};
__constant__ int c_l3a[NTRIP] = {
    0,0,0,0,0, 1,1,1,1,1,1,1,1, 2,2,2,2,2,2,2,2,2,2, 3,3,3,3,3,3,3,3,3,3,
    4,4,4,4,4,4,4,4,4, 5,5,5,5,5,5, 6,6,6,6, 7,7, 8};
__constant__ int c_widx[NTRIP] = {
    0,5,17,32,46, 1,6,8,18,22,33,39,47, 2,7,9,11,19,23,27,34,40,48,
    3,10,12,14,20,24,28,35,41,49, 4,13,15,21,25,29,36,42,50,
    16,26,30,37,43,51, 31,38,44,52, 45,53, 54};
__constant__ int c_based[NTRIP] = {
    0,1024,2048,3072,4096,
    5120,8192,11264,14336,17408,20480,23552,26624,
    29696,34816,39936,45056,50176,55296,60416,65536,70656,75776,
    80896,88064,95232,102400,109568,116736,123904,131072,138240,145408,
    152576,161792,171008,180224,189440,198656,207872,217088,226304,
    235520,246784,258048,269312,280576,291840,
    303104,316416,329728,343040,
    356352,371712,
    387072};

__device__ float d_blksum[NTRIP * 64];
__device__ float d_blk0[5 * 64];
__device__ float d_y[64 * 800];
__device__ float d_z[64LL * DTOT];
__device__ float d_csq[DTOT];
__device__ float d_csum[DTOT];
__device__ float d_g[DTOT];
__device__ float d_m[5120];
__device__ float d_part[(long)NKB * 8192];

__device__ __forceinline__ float tf32r(float x) {
    asm("cvt.rna.tf32.f32 %0, %0;" : "+f"(x));
    return x;
}

__device__ __forceinline__ void computeAD(int b, int l3v, float& A, float& D) {
    const int tro[10] = {0, 5, 13, 23, 33, 42, 48, 52, 54, 55};
    float power = 0.f;
    #pragma unroll
    for (int tr = 0; tr < NTRIP; tr++) power += d_blksum[tr*64 + b];
    float s = 0.f;
    for (int tr = tro[l3v]; tr < tro[l3v+1]; tr++) s += d_blksum[tr*64 + b];
    float scale = rsqrtf(power / (float)DTOT + EPSV);
    float cnt = (float)((tro[l3v+1] - tro[l3v]) * 1024 * (2*l3v + 1));
    float ms = scale * scale * s / cnt;
    if (l3v == 0) {
        float s0 = 0.f;
        #pragma unroll
        for (int tr = 0; tr < 5; tr++) s0 += d_blk0[tr*64 + b];
        float mu = scale * s0 / cnt;
        float c  = rsqrtf(ms - mu*mu + EPSV);
        A = scale * c; D = -mu * c;
    } else {
        A = scale * rsqrtf(ms + EPSV); D = 0.f;
    }
}

__device__ __forceinline__ int regionOf(long d) {
    if (d < 5120)   return 0;
    if (d < 29696)  return 1;
    if (d < 80896)  return 2;
    if (d < 152576) return 3;
    if (d < 235520) return 4;
    if (d < 303104) return 5;
    if (d < 356352) return 6;
    if (d < 387072) return 7;
    return 8;
}

// ------------- shim (ncu slot alignment: puts k_trip_all at launch #4) -------------
__global__ void k_shim() {}

// ------------- y = Wlin@x (+bias0) -------------
__global__ void k_y(const float* __restrict__ x0, const float* __restrict__ x1,
                    const float* __restrict__ x2, const float* __restrict__ x3,
                    const float* __restrict__ x4, const float* __restrict__ Wlin,
                    const float* __restrict__ bias0) {
    int b = blockIdx.x, t = threadIdx.x;
    const float* xs[5] = {x0, x1, x2, x3, x4};
    const int yo[5] = {0, 32, 128, 288, 512};
    for (int l = 0; l < 5; l++) {
        int M = 2*l + 1;
        const float* x = xs[l] + (long)b * 32 * M;
        for (int e = t; e < 32 * M; e += blockDim.x) {
            int o = e / M, m = e % M;
            float acc = (l == 0) ? bias0[o] : 0.f;
            const float* wr = Wlin + (l*32 + o) * 32;
            #pragma unroll 8
            for (int i = 0; i < 32; i++) acc += wr[i] * x[i*M + m];
            d_y[b*800 + yo[l] + o*M + m] = acc;
        }
    }
}

// ------------- triple products + row-norm + LN stats -------------
template <int K3>
__device__ __forceinline__ void trip_body(int tr, int b, const float* __restrict__ w3j,
                                          float* sy1, float* sy2, float* sw, float* su,
                                          float* rw1, float* rw2) {
    constexpr int K3A = (K3 + 3) & ~3;
    constexpr int NV  = K3A / 4;
    const int l1 = c_l1[tr], l2 = c_l2[tr];
    const int m1 = 2*l1 + 1, n2 = 2*l2 + 1;
    const int yo[5] = {0, 32, 128, 288, 512};
    int t = threadIdx.x, lane = t & 31, w = t >> 5;

    for (int e = t; e < 32*m1; e += 256) sy1[e] = d_y[b*800 + yo[l1] + e];
    for (int e = t; e < 32*n2; e += 256) sy2[e] = d_y[b*800 + yo[l2] + e];
    const float* wp = w3j + (long)c_widx[tr] * 9 * 9 * 17;
    for (int e = t; e < m1*n2*K3; e += 256) {
        int m = e / (n2*K3), r = e % (n2*K3), nn = r / K3, k = r % K3;
        sw[e] = wp[m*153 + nn*17 + k];
    }
    __syncthreads();
    // u[i,n,k] = sum_m y1[i,m] w[m,n,k]
    for (int e = t; e < 32*n2*K3; e += 256) {
        int i = e / (n2*K3), r = e % (n2*K3), nn = r / K3, k = r % K3;
        float a = 0.f;
        for (int m = 0; m < m1; m++) a += sy1[i*m1 + m] * sw[(m*n2 + nn)*K3 + k];
        su[(i*n2 + nn)*K3A + k] = a;
    }
    __syncthreads();

    float lsq = 0.f, ls0 = 0.f;
    long zbase = (long)b * DTOT + c_based[tr];
    for (int p = t; p < 1024; p += 256) {
        int j = p & 31;         // lane
        int iw = p >> 5;        // warp-constant -> su reads broadcast
        float4 acc4[NV];
        #pragma unroll
        for (int q = 0; q < NV; q++) acc4[q] = make_float4(0.f, 0.f, 0.f, 0.f);
        const float* y2p = &sy2[j*n2];
        for (int n = 0; n < n2; n++) {
            float yn = y2p[n];
            const float4* up = (const float4*)&su[(iw*n2 + n)*K3A];
            #pragma unroll
            for (int q = 0; q < NV; q++) {
                float4 u4 = up[q];
                acc4[q].x += yn*u4.x; acc4[q].y += yn*u4.y;
                acc4[q].z += yn*u4.z; acc4[q].w += yn*u4.w;
            }
        }
        float S = 0.f;
        #pragma unroll
        for (int q = 0; q < NV; q++) {
            if (4*q + 0 < K3) S += acc4[q].x*acc4[q].x;
            if (4*q + 1 < K3) S += acc4[q].y*acc4[q].y;
            if (4*q + 2 < K3) S += acc4[q].z*acc4[q].z;
            if (4*q + 3 < K3) S += acc4[q].w*acc4[q].w;
        }
        float inv = rsqrtf(S + EPSV);
        float* zp = &d_z[zbase + (long)p * K3];
        #pragma unroll
        for (int q = 0; q < NV; q++) {
            if (4*q + 0 < K3) zp[4*q + 0] = acc4[q].x * inv;
            if (4*q + 1 < K3) zp[4*q + 1] = acc4[q].y * inv;
            if (4*q + 2 < K3) zp[4*q + 2] = acc4[q].z * inv;
            if (4*q + 3 < K3) zp[4*q + 3] = acc4[q].w * inv;
        }
        lsq += S * inv * inv;
        if (K3 == 1) ls0 += acc4[0].x * inv;
    }
    #pragma unroll
    for (int o = 16; o > 0; o >>= 1) {
        lsq += __shfl_xor_sync(0xFFFFFFFFu, lsq, o);
        if (K3 == 1) ls0 += __shfl_xor_sync(0xFFFFFFFFu, ls0, o);
    }
    if (lane == 0) { rw1[w] = lsq; rw2[w] = ls0; }
    __syncthreads();
    if (t == 0) {
        float s1 = 0.f, s2 = 0.f;
        #pragma unroll
        for (int q = 0; q < 8; q++) { s1 += rw1[q]; s2 += rw2[q]; }
        d_blksum[tr*64 + b] = s1;
        if (K3 == 1) d_blk0[tr*64 + b] = s2;
    }
}

__global__ void __launch_bounds__(256) k_trip_all(const float* __restrict__ w3j) {
    __shared__ float sy1[288], sy2[288], sw[1377];
    __shared__ __align__(16) float su[5760];
    __shared__ float rw1[8], rw2[8];
    int tr = blockIdx.x, b = blockIdx.y;
    switch (c_l3a[tr]) {
        case 0: trip_body<1> (tr, b, w3j, sy1, sy2, sw, su, rw1, rw2); break;
        case 1: trip_body<3> (tr, b, w3j, sy1, sy2, sw, su, rw1, rw2); break;
        case 2: trip_body<5> (tr, b, w3j, sy1, sy2, sw, su, rw1, rw2); break;
        case 3: trip_body<7> (tr, b, w3j, sy1, sy2, sw, su, rw1, rw2); break;
        case 4: trip_body<9> (tr, b, w3j, sy1, sy2, sw, su, rw1, rw2); break;
        case 5: trip_body<11>(tr, b, w3j, sy1, sy2, sw, su, rw1, rw2); break;
        case 6: trip_body<13>(tr, b, w3j, sy1, sy2, sw, su, rw1, rw2); break;
        case 7: trip_body<15>(tr, b, w3j, sy1, sy2, sw, su, rw1, rw2); break;
        case 8: trip_body<17>(tr, b, w3j, sy1, sy2, sw, su, rw1, rw2); break;
    }
}

// ------------- BN column stats: stream z once, per-d csq/csum -------------
__global__ void __launch_bounds__(256) k_bncol() {
    int bid = blockIdx.x, t = threadIdx.x;
    long d0 = (long)bid * 1024;
    int l3v = regionOf(d0);
    __shared__ float sA[64], sD[64];
    if (t < 64) computeAD(t, l3v, sA[t], sD[t]);
    __syncthreads();
    long dd = d0 + (long)t * 4;
    float4 sq = make_float4(0.f,0.f,0.f,0.f), sm = make_float4(0.f,0.f,0.f,0.f);
    #pragma unroll 8
    for (int b = 0; b < 64; b++) {
        float4 z4 = *(const float4*)&d_z[(long)b*DTOT + dd];
        float a = sA[b], dv = sD[b];
        float vx = a*z4.x + dv, vy = a*z4.y + dv, vz = a*z4.z + dv, vw = a*z4.w + dv;
        sq.x += vx*vx; sq.y += vy*vy; sq.z += vz*vz; sq.w += vw*vw;
        sm.x += vx;    sm.y += vy;    sm.z += vz;    sm.w += vw;
    }
    *(float4*)&d_csq[dd]  = sq;
    *(float4*)&d_csum[dd] = sm;
}

// ------------- BN reduce: per-(tr,i,j) gain (and mean for l3=0) -------------
__global__ void k_bnred() {
    int id = blockIdx.x, tr = id >> 5, i = id & 31;
    int j = threadIdx.x;
    int l3v = c_l3a[tr], k3 = 2*l3v + 1;
    long base = (long)c_based[tr] + (long)(i*32 + j) * k3;
    float sq = 0.f, sm = 0.f;
    for (int k = 0; k < k3; k++) { sq += d_csq[base + k]; sm += d_csum[base + k]; }
    float gj, mj = 0.f;
    if (l3v == 0) {
        float m = sm * (1.f/64.f);
        gj = rsqrtf(sq*(1.f/64.f) - m*m + EPSV); mj = m;
    } else {
        gj = rsqrtf(sq / (64.f * (float)k3) + EPSV);
    }
    for (int k = 0; k < k3; k++) {
        d_g[base + k] = gj;
        if (l3v == 0) d_m[base + k] = mj;
    }
}

// ------------- split-K GEMM: mma.sync tf32, cp.async W ring, fused BN affine -------------
__global__ void __launch_bounds__(256, 3) k_gemm_mma(const float* __restrict__ W) {
    __shared__ __align__(16) float As[2][128][36];
    __shared__ __align__(16) float Bs[64][36];
    __shared__ float sA[64], sD[64];
    int t = threadIdx.x;
    int w = t >> 5, lane = t & 31, gid = lane >> 2, tid4 = lane & 3;
    long kbase = (long)blockIdx.x * KSPAN;
    int l3v = regionOf(kbase);
    bool hasm = (l3v == 0);

    if (t < 64) computeAD(t, l3v, sA[t], sD[t]);
    __syncthreads();

    float c[8][4];
    #pragma unroll
    for (int nt = 0; nt < 8; nt++)
        #pragma unroll
        for (int q = 0; q < 4; q++) c[nt][q] = 0.f;

    float4 sv[2];   // staged (affine+tf32 applied) B values for the upcoming chunk
    // prologue: cp.async W chunk 0 -> As[0]; compute staged B for chunk 0
    {
        #pragma unroll
        for (int i = 0; i < 4; i++) {
            int id = t + i*256, r = id >> 3, cc = (id & 7) * 4;
            unsigned dst = (unsigned)__cvta_generic_to_shared(&As[0][r][cc]);
            const float* src = W + (long)r*DTOT + kbase + cc;
            asm volatile("cp.async.cg.shared.global [%0], [%1], 16;" :: "r"(dst), "l"(src));
        }
        asm volatile("cp.async.commit_group;" ::: "memory");
        #pragma unroll
        for (int i = 0; i < 2; i++) {
            int id = t + i*256, r = id >> 3, cc = (id & 7) * 4;
            float4 z4 = *(const float4*)(d_z + (long)r*DTOT + kbase + cc);
            float4 g4 = *(const float4*)(d_g + kbase + cc);
            float4 m4 = hasm ? *(const float4*)(d_m + kbase + cc) : make_float4(0.f,0.f,0.f,0.f);
            float a = sA[r], dd = sD[r];
            sv[i].x = tf32r(g4.x * (a*z4.x + dd - m4.x));
            sv[i].y = tf32r(g4.y * (a*z4.y + dd - m4.y));
            sv[i].z = tf32r(g4.z * (a*z4.z + dd - m4.z));
            sv[i].w = tf32r(g4.w * (a*z4.w + dd - m4.w));
        }
    }

    for (int ch = 0; ch < NCH; ch++) {
        int s = ch & 1;
        // issue next W chunk into the other buffer
        if (ch + 1 < NCH) {
            long kg = kbase + (ch + 1) * 32;
            #pragma unroll
            for (int i = 0; i < 4; i++) {
                int id = t + i*256, r = id >> 3, cc = (id & 7) * 4;
                unsigned dst = (unsigned)__cvta_generic_to_shared(&As[s^1][r][cc]);
                const float* src = W + (long)r*DTOT + kg + cc;
                asm volatile("cp.async.cg.shared.global [%0], [%1], 16;" :: "r"(dst), "l"(src));
            }
        }
        asm volatile("cp.async.commit_group;" ::: "memory");
        // stage B for chunk ch
        #pragma unroll
        for (int i = 0; i < 2; i++) {
            int id = t + i*256, r = id >> 3, cc = (id & 7) * 4;
            *(float4*)&Bs[r][cc] = sv[i];
        }
        asm volatile("cp.async.wait_group 1;" ::: "memory");
        __syncthreads();
        // prefetch+transform B for chunk ch+1 (overlaps mma)
        if (ch + 1 < NCH) {
            long kg = kbase + (ch + 1) * 32;
            #pragma unroll
            for (int i = 0; i < 2; i++) {
                int id = t + i*256, r = id >> 3, cc = (id & 7) * 4;
                float4 z4 = *(const float4*)(d_z + (long)r*DTOT + kg + cc);
                float4 g4 = *(const float4*)(d_g + kg + cc);
                float4 m4 = hasm ? *(const float4*)(d_m + kg + cc) : make_float4(0.f,0.f,0.f,0.f);
                float a = sA[r], dd = sD[r];
                sv[i].x = tf32r(g4.x * (a*z4.x + dd - m4.x));
                sv[i].y = tf32r(g4.y * (a*z4.y + dd - m4.y));
                sv[i].z = tf32r(g4.z * (a*z4.z + dd - m4.z));
                sv[i].w = tf32r(g4.w * (a*z4.w + dd - m4.w));
            }
        }
        // compute
        #pragma unroll
        for (int ks = 0; ks < 4; ks++) {
            int k0 = ks * 8;
            int ar = w*16 + gid;
            unsigned a0 = __float_as_uint(tf32r(As[s][ar][k0 + tid4]));
            unsigned a1 = __float_as_uint(tf32r(As[s][ar + 8][k0 + tid4]));
            unsigned a2 = __float_as_uint(tf32r(As[s][ar][k0 + tid4 + 4]));
            unsigned a3 = __float_as_uint(tf32r(As[s][ar + 8][k0 + tid4 + 4]));
            #pragma unroll
            for (int nt = 0; nt < 8; nt++) {
                unsigned b0 = __float_as_uint(Bs[nt*8 + gid][k0 + tid4]);
                unsigned b1 = __float_as_uint(Bs[nt*8 + gid][k0 + tid4 + 4]);
                asm volatile(
                    "mma.sync.aligned.m16n8k8.row.col.f32.tf32.tf32.f32 "
                    "{%0,%1,%2,%3}, {%4,%5,%6,%7}, {%8,%9}, {%0,%1,%2,%3};"
                    : "+f"(c[nt][0]), "+f"(c[nt][1]), "+f"(c[nt][2]), "+f"(c[nt][3])
                    : "r"(a0), "r"(a1), "r"(a2), "r"(a3), "r"(b0), "r"(b1));
            }
        }
        __syncthreads();
    }

    long pb = (long)blockIdx.x * 8192;
    int j0 = w*16 + gid, n0 = tid4 * 2;
    #pragma unroll
    for (int nt = 0; nt < 8; nt++) {
        int n = nt*8 + n0;
        *(float2*)&d_part[pb + (long)j0*64 + n]       = make_float2(c[nt][0], c[nt][1]);
        *(float2*)&d_part[pb + (long)(j0 + 8)*64 + n] = make_float2(c[nt][2], c[nt][3]);
    }
}

// ------------- reduce partials + bias, split (mu, logvar) -------------
__global__ void k_fin(const float* __restrict__ bfc, float* __restrict__ out) {
    int e = blockIdx.x * blockDim.x + threadIdx.x;
    if (e >= 8192) return;
    float s = 0.f;
    #pragma unroll 8
    for (int blk = 0; blk < NKB; blk++) s += d_part[(long)blk * 8192 + e];
    int j = e >> 6, b = e & 63;
    out[(j >> 6) * 4096 + b*64 + (j & 63)] = s + bfc[j];
}

extern "C" void kernel_launch(void* const* d_in, const int* in_sizes, int n_in,
                              void* d_out, int out_size) {
    const float* x0    = (const float*)d_in[0];
    const float* x1    = (const float*)d_in[1];
    const float* x2    = (const float*)d_in[2];
    const float* x3    = (const float*)d_in[3];
    const float* x4    = (const float*)d_in[4];
    const float* Wlin  = (const float*)d_in[5];
    const float* bias0 = (const float*)d_in[6];
    const float* w3j   = (const float*)d_in[7];
    const float* Wfc   = (const float*)d_in[8];
    const float* bfc   = (const float*)d_in[9];
    float* out = (float*)d_out;

    k_shim<<<1, 32>>>();                 // launch #1
    k_shim<<<1, 32>>>();                 // launch #2
    k_y<<<64, 256>>>(x0, x1, x2, x3, x4, Wlin, bias0);          // #3
    k_trip_all<<<dim3(NTRIP, 64), 256>>>(w3j);                  // #4 -> profiled
    k_bncol<<<DTOT/1024, 256>>>();
    k_bnred<<<NTRIP*32, 32>>>();
    k_gemm_mma<<<NKB, 256>>>(Wfc);
    k_fin<<<32, 256>>>(bfc, out);
}

// round 17
// speedup vs baseline: 1.5553x; 1.1737x over previous
#include <cuda_runtime.h>
#include <cstdint>

#define NTRIP 55
#define DTOT  404480
#define EPSV  1e-6f
#define NKB   395
#define KSPAN 1024
#define NCH   32

__constant__ int c_l3a[NTRIP] = {
    0,0,0,0,0, 1,1,1,1,1,1,1,1, 2,2,2,2,2,2,2,2,2,2, 3,3,3,3,3,3,3,3,3,3,
    4,4,4,4,4,4,4,4,4, 5,5,5,5,5,5, 6,6,6,6, 7,7, 8};
__constant__ int c_widx[NTRIP] = {
    0,5,17,32,46, 1,6,8,18,22,33,39,47, 2,7,9,11,19,23,27,34,40,48,
    3,10,12,14,20,24,28,35,41,49, 4,13,15,21,25,29,36,42,50,
    16,26,30,37,43,51, 31,38,44,52, 45,53, 54};
__constant__ int c_based[NTRIP] = {
    0,1024,2048,3072,4096,
    5120,8192,11264,14336,17408,20480,23552,26624,
    29696,34816,39936,45056,50176,55296,60416,65536,70656,75776,
    80896,88064,95232,102400,109568,116736,123904,131072,138240,145408,
    152576,161792,171008,180224,189440,198656,207872,217088,226304,
    235520,246784,258048,269312,280576,291840,
    303104,316416,329728,343040,
    356352,371712,
    387072};

__device__ float d_blksum[NTRIP * 64];
__device__ float d_blk0[5 * 64];
__device__ float d_y[64 * 800];
__device__ float d_z[64LL * DTOT];
__device__ float d_csq[DTOT];
__device__ float d_csum[DTOT];
__device__ float d_g[DTOT];
__device__ float d_m[5120];
__device__ float d_part[(long)NKB * 8192];

__device__ __forceinline__ float tf32r(float x) {
    asm("cvt.rna.tf32.f32 %0, %0;" : "+f"(x));
    return x;
}

__device__ __forceinline__ void computeAD(int b, int l3v, float& A, float& D) {
    const int tro[10] = {0, 5, 13, 23, 33, 42, 48, 52, 54, 55};
    float power = 0.f;
    #pragma unroll
    for (int tr = 0; tr < NTRIP; tr++) power += d_blksum[tr*64 + b];
    float s = 0.f;
    for (int tr = tro[l3v]; tr < tro[l3v+1]; tr++) s += d_blksum[tr*64 + b];
    float scale = rsqrtf(power / (float)DTOT + EPSV);
    float cnt = (float)((tro[l3v+1] - tro[l3v]) * 1024 * (2*l3v + 1));
    float ms = scale * scale * s / cnt;
    if (l3v == 0) {
        float s0 = 0.f;
        #pragma unroll
        for (int tr = 0; tr < 5; tr++) s0 += d_blk0[tr*64 + b];
        float mu = scale * s0 / cnt;
        float c  = rsqrtf(ms - mu*mu + EPSV);
        A = scale * c; D = -mu * c;
    } else {
        A = scale * rsqrtf(ms + EPSV); D = 0.f;
    }
}

__device__ __forceinline__ int regionOf(long d) {
    if (d < 5120)   return 0;
    if (d < 29696)  return 1;
    if (d < 80896)  return 2;
    if (d < 152576) return 3;
    if (d < 235520) return 4;
    if (d < 303104) return 5;
    if (d < 356352) return 6;
    if (d < 387072) return 7;
    return 8;
}

// ------------- shim (ncu slot alignment: keeps k_trip_all at launch #4) -------------
__global__ void k_shim() {}

// ------------- y = Wlin@x (+bias0) -------------
__global__ void k_y(const float* __restrict__ x0, const float* __restrict__ x1,
                    const float* __restrict__ x2, const float* __restrict__ x3,
                    const float* __restrict__ x4, const float* __restrict__ Wlin,
                    const float* __restrict__ bias0) {
    int b = blockIdx.x, t = threadIdx.x;
    const float* xs[5] = {x0, x1, x2, x3, x4};
    const int yo[5] = {0, 32, 128, 288, 512};
    for (int l = 0; l < 5; l++) {
        int M = 2*l + 1;
        const float* x = xs[l] + (long)b * 32 * M;
        for (int e = t; e < 32 * M; e += blockDim.x) {
            int o = e / M, m = e % M;
            float acc = (l == 0) ? bias0[o] : 0.f;
            const float* wr = Wlin + (l*32 + o) * 32;
            #pragma unroll 8
            for (int i = 0; i < 32; i++) acc += wr[i] * x[i*M + m];
            d_y[b*800 + yo[l] + o*M + m] = acc;
        }
    }
}

// ------------- triple products + row-norm + LN stats, fully specialized -------------
template <int L1, int L2, int L3>
__device__ __forceinline__ void trip_body(int tr, int b, const float* __restrict__ w3j,
                                          float* sy1, float* sy2, float* sw, float* su,
                                          float* sz, float* rw1, float* rw2) {
    constexpr int m1 = 2*L1 + 1, n2 = 2*L2 + 1, K3 = 2*L3 + 1;
    constexpr int K3A = (K3 + 3) & ~3;
    constexpr int NV  = K3A / 4;
    constexpr int yoA[5] = {0, 32, 128, 288, 512};
    constexpr int yo1 = yoA[L1], yo2 = yoA[L2];
    int t = threadIdx.x, lane = t & 31, w = t >> 5;

    for (int e = t; e < 32*m1; e += 256) sy1[e] = d_y[b*800 + yo1 + e];
    for (int e = t; e < 32*n2; e += 256) sy2[e] = d_y[b*800 + yo2 + e];
    const float* wp = w3j + (long)c_widx[tr] * 9 * 9 * 17;
    for (int e = t; e < m1*n2*K3; e += 256) {
        int m = e / (n2*K3), r = e % (n2*K3), nn = r / K3, k = r % K3;
        sw[e] = wp[m*153 + nn*17 + k];
    }
    __syncthreads();
    // u[i,n,k] = sum_m y1[i,m] w[m,n,k]
    for (int e = t; e < 32*n2*K3; e += 256) {
        int i = e / (n2*K3), r = e % (n2*K3), nn = r / K3, k = r % K3;
        float a = 0.f;
        #pragma unroll
        for (int m = 0; m < m1; m++) a += sy1[i*m1 + m] * sw[(m*n2 + nn)*K3 + k];
        su[(i*n2 + nn)*K3A + k] = a;
    }
    __syncthreads();

    float lsq = 0.f, ls0 = 0.f;
    long zbase = (long)b * DTOT + c_based[tr];
    #pragma unroll 1
    for (int rnd = 0; rnd < 4; rnd++) {
        int j = lane;            // p & 31
        int iw = rnd*8 + w;      // p >> 5, warp-constant -> su reads broadcast
        float4 acc4[NV];
        #pragma unroll
        for (int q = 0; q < NV; q++) acc4[q] = make_float4(0.f, 0.f, 0.f, 0.f);
        const float* y2p = &sy2[j*n2];
        #pragma unroll
        for (int n = 0; n < n2; n++) {
            float yn = y2p[n];
            const float4* up = (const float4*)&su[(iw*n2 + n)*K3A];
            #pragma unroll
            for (int q = 0; q < NV; q++) {
                float4 u4 = up[q];
                acc4[q].x += yn*u4.x; acc4[q].y += yn*u4.y;
                acc4[q].z += yn*u4.z; acc4[q].w += yn*u4.w;
            }
        }
        float S = 0.f;
        #pragma unroll
        for (int q = 0; q < NV; q++) {
            if (4*q + 0 < K3) S += acc4[q].x*acc4[q].x;
            if (4*q + 1 < K3) S += acc4[q].y*acc4[q].y;
            if (4*q + 2 < K3) S += acc4[q].z*acc4[q].z;
            if (4*q + 3 < K3) S += acc4[q].w*acc4[q].w;
        }
        float inv = rsqrtf(S + EPSV);
        // stage row-normed values into smem (stride K3 odd -> conflict-free)
        float* szp = &sz[t * K3];
        #pragma unroll
        for (int q = 0; q < NV; q++) {
            if (4*q + 0 < K3) szp[4*q + 0] = acc4[q].x * inv;
            if (4*q + 1 < K3) szp[4*q + 1] = acc4[q].y * inv;
            if (4*q + 2 < K3) szp[4*q + 2] = acc4[q].z * inv;
            if (4*q + 3 < K3) szp[4*q + 3] = acc4[q].w * inv;
        }
        lsq += S * inv * inv;
        if (K3 == 1) ls0 += acc4[0].x * inv;
        __syncthreads();
        // coalesced float4 flush: 256*K3 floats = 64*K3 float4s
        float* zdst = &d_z[zbase + (long)rnd * (256*K3)];
        #pragma unroll
        for (int v = t; v < 64*K3; v += 256)
            *(float4*)&zdst[4*v] = ((const float4*)sz)[v];
        __syncthreads();
    }
    #pragma unroll
    for (int o = 16; o > 0; o >>= 1) {
        lsq += __shfl_xor_sync(0xFFFFFFFFu, lsq, o);
        if (K3 == 1) ls0 += __shfl_xor_sync(0xFFFFFFFFu, ls0, o);
    }
    if (lane == 0) { rw1[w] = lsq; rw2[w] = ls0; }
    __syncthreads();
    if (t == 0) {
        float s1 = 0.f, s2 = 0.f;
        #pragma unroll
        for (int q = 0; q < 8; q++) { s1 += rw1[q]; s2 += rw2[q]; }
        d_blksum[tr*64 + b] = s1;
        if (K3 == 1) d_blk0[tr*64 + b] = s2;
    }
}

#define TRIPS(X) \
 X(0,0,0,0) X(1,1,1,0) X(2,2,2,0) X(3,3,3,0) X(4,4,4,0) \
 X(5,0,1,1) X(6,1,1,1) X(7,1,2,1) X(8,2,2,1) X(9,2,3,1) X(10,3,3,1) X(11,3,4,1) X(12,4,4,1) \
 X(13,0,2,2) X(14,1,1,2) X(15,1,2,2) X(16,1,3,2) X(17,2,2,2) X(18,2,3,2) X(19,2,4,2) X(20,3,3,2) X(21,3,4,2) X(22,4,4,2) \
 X(23,0,3,3) X(24,1,2,3) X(25,1,3,3) X(26,1,4,3) X(27,2,2,3) X(28,2,3,3) X(29,2,4,3) X(30,3,3,3) X(31,3,4,3) X(32,4,4,3) \
 X(33,0,4,4) X(34,1,3,4) X(35,1,4,4) X(36,2,2,4) X(37,2,3,4) X(38,2,4,4) X(39,3,3,4) X(40,3,4,4) X(41,4,4,4) \
 X(42,1,4,5) X(43,2,3,5) X(44,2,4,5) X(45,3,3,5) X(46,3,4,5) X(47,4,4,5) \
 X(48,2,4,6) X(49,3,3,6) X(50,3,4,6) X(51,4,4,6) \
 X(52,3,4,7) X(53,4,4,7) \
 X(54,4,4,8)

#define TCASE(TR, A, B, C) \
    case TR: trip_body<A, B, C>(TR, b, w3j, sy1, sy2, sw, su, sz, rw1, rw2); break;

__global__ void __launch_bounds__(256) k_trip_all(const float* __restrict__ w3j) {
    __shared__ float sy1[288], sy2[288], sw[1377];
    __shared__ __align__(16) float su[5760];
    __shared__ __align__(16) float sz[4352];
    __shared__ float rw1[8], rw2[8];
    int tr = blockIdx.x, b = blockIdx.y;
    switch (tr) { TRIPS(TCASE) }
}

// ------------- BN column stats: stream z once, per-d csq/csum -------------
__global__ void __launch_bounds__(256) k_bncol() {
    int bid = blockIdx.x, t = threadIdx.x;
    long d0 = (long)bid * 1024;
    int l3v = regionOf(d0);
    __shared__ float sA[64], sD[64];
    if (t < 64) computeAD(t, l3v, sA[t], sD[t]);
    __syncthreads();
    long dd = d0 + (long)t * 4;
    float4 sq = make_float4(0.f,0.f,0.f,0.f), sm = make_float4(0.f,0.f,0.f,0.f);
    #pragma unroll 8
    for (int b = 0; b < 64; b++) {
        float4 z4 = *(const float4*)&d_z[(long)b*DTOT + dd];
        float a = sA[b], dv = sD[b];
        float vx = a*z4.x + dv, vy = a*z4.y + dv, vz = a*z4.z + dv, vw = a*z4.w + dv;
        sq.x += vx*vx; sq.y += vy*vy; sq.z += vz*vz; sq.w += vw*vw;
        sm.x += vx;    sm.y += vy;    sm.z += vz;    sm.w += vw;
    }
    *(float4*)&d_csq[dd]  = sq;
    *(float4*)&d_csum[dd] = sm;
}

// ------------- BN reduce: per-(tr,i,j) gain (and mean for l3=0) -------------
__global__ void k_bnred() {
    int id = blockIdx.x, tr = id >> 5, i = id & 31;
    int j = threadIdx.x;
    int l3v = c_l3a[tr], k3 = 2*l3v + 1;
    long base = (long)c_based[tr] + (long)(i*32 + j) * k3;
    float sq = 0.f, sm = 0.f;
    for (int k = 0; k < k3; k++) { sq += d_csq[base + k]; sm += d_csum[base + k]; }
    float gj, mj = 0.f;
    if (l3v == 0) {
        float m = sm * (1.f/64.f);
        gj = rsqrtf(sq*(1.f/64.f) - m*m + EPSV); mj = m;
    } else {
        gj = rsqrtf(sq / (64.f * (float)k3) + EPSV);
    }
    for (int k = 0; k < k3; k++) {
        d_g[base + k] = gj;
        if (l3v == 0) d_m[base + k] = mj;
    }
}

// ------------- split-K GEMM: mma.sync tf32, cp.async W ring, fused BN affine -------------
__global__ void __launch_bounds__(256, 3) k_gemm_mma(const float* __restrict__ W) {
    __shared__ __align__(16) float As[2][128][36];
    __shared__ __align__(16) float Bs[64][36];
    __shared__ float sA[64], sD[64];
    int t = threadIdx.x;
    int w = t >> 5, lane = t & 31, gid = lane >> 2, tid4 = lane & 3;
    long kbase = (long)blockIdx.x * KSPAN;
    int l3v = regionOf(kbase);
    bool hasm = (l3v == 0);

    if (t < 64) computeAD(t, l3v, sA[t], sD[t]);
    __syncthreads();

    float c[8][4];
    #pragma unroll
    for (int nt = 0; nt < 8; nt++)
        #pragma unroll
        for (int q = 0; q < 4; q++) c[nt][q] = 0.f;

    float4 sv[2];
    {
        #pragma unroll
        for (int i = 0; i < 4; i++) {
            int id = t + i*256, r = id >> 3, cc = (id & 7) * 4;
            unsigned dst = (unsigned)__cvta_generic_to_shared(&As[0][r][cc]);
            const float* src = W + (long)r*DTOT + kbase + cc;
            asm volatile("cp.async.cg.shared.global [%0], [%1], 16;" :: "r"(dst), "l"(src));
        }
        asm volatile("cp.async.commit_group;" ::: "memory");
        #pragma unroll
        for (int i = 0; i < 2; i++) {
            int id = t + i*256, r = id >> 3, cc = (id & 7) * 4;
            float4 z4 = *(const float4*)(d_z + (long)r*DTOT + kbase + cc);
            float4 g4 = *(const float4*)(d_g + kbase + cc);
            float4 m4 = hasm ? *(const float4*)(d_m + kbase + cc) : make_float4(0.f,0.f,0.f,0.f);
            float a = sA[r], dd = sD[r];
            sv[i].x = tf32r(g4.x * (a*z4.x + dd - m4.x));
            sv[i].y = tf32r(g4.y * (a*z4.y + dd - m4.y));
            sv[i].z = tf32r(g4.z * (a*z4.z + dd - m4.z));
            sv[i].w = tf32r(g4.w * (a*z4.w + dd - m4.w));
        }
    }

    for (int ch = 0; ch < NCH; ch++) {
        int s = ch & 1;
        if (ch + 1 < NCH) {
            long kg = kbase + (ch + 1) * 32;
            #pragma unroll
            for (int i = 0; i < 4; i++) {
                int id = t + i*256, r = id >> 3, cc = (id & 7) * 4;
                unsigned dst = (unsigned)__cvta_generic_to_shared(&As[s^1][r][cc]);
                const float* src = W + (long)r*DTOT + kg + cc;
                asm volatile("cp.async.cg.shared.global [%0], [%1], 16;" :: "r"(dst), "l"(src));
            }
        }
        asm volatile("cp.async.commit_group;" ::: "memory");
        #pragma unroll
        for (int i = 0; i < 2; i++) {
            int id = t + i*256, r = id >> 3, cc = (id & 7) * 4;
            *(float4*)&Bs[r][cc] = sv[i];
        }
        asm volatile("cp.async.wait_group 1;" ::: "memory");
        __syncthreads();
        if (ch + 1 < NCH) {
            long kg = kbase + (ch + 1) * 32;
            #pragma unroll
            for (int i = 0; i < 2; i++) {
                int id = t + i*256, r = id >> 3, cc = (id & 7) * 4;
                float4 z4 = *(const float4*)(d_z + (long)r*DTOT + kg + cc);
                float4 g4 = *(const float4*)(d_g + kg + cc);
                float4 m4 = hasm ? *(const float4*)(d_m + kg + cc) : make_float4(0.f,0.f,0.f,0.f);
                float a = sA[r], dd = sD[r];
                sv[i].x = tf32r(g4.x * (a*z4.x + dd - m4.x));
                sv[i].y = tf32r(g4.y * (a*z4.y + dd - m4.y));
                sv[i].z = tf32r(g4.z * (a*z4.z + dd - m4.z));
                sv[i].w = tf32r(g4.w * (a*z4.w + dd - m4.w));
            }
        }
        #pragma unroll
        for (int ks = 0; ks < 4; ks++) {
            int k0 = ks * 8;
            int ar = w*16 + gid;
            unsigned a0 = __float_as_uint(tf32r(As[s][ar][k0 + tid4]));
            unsigned a1 = __float_as_uint(tf32r(As[s][ar + 8][k0 + tid4]));
            unsigned a2 = __float_as_uint(tf32r(As[s][ar][k0 + tid4 + 4]));
            unsigned a3 = __float_as_uint(tf32r(As[s][ar + 8][k0 + tid4 + 4]));
            #pragma unroll
            for (int nt = 0; nt < 8; nt++) {
                unsigned b0 = __float_as_uint(Bs[nt*8 + gid][k0 + tid4]);
                unsigned b1 = __float_as_uint(Bs[nt*8 + gid][k0 + tid4 + 4]);
                asm volatile(
                    "mma.sync.aligned.m16n8k8.row.col.f32.tf32.tf32.f32 "
                    "{%0,%1,%2,%3}, {%4,%5,%6,%7}, {%8,%9}, {%0,%1,%2,%3};"
                    : "+f"(c[nt][0]), "+f"(c[nt][1]), "+f"(c[nt][2]), "+f"(c[nt][3])
                    : "r"(a0), "r"(a1), "r"(a2), "r"(a3), "r"(b0), "r"(b1));
            }
        }
        __syncthreads();
    }

    long pb = (long)blockIdx.x * 8192;
    int j0 = w*16 + gid, n0 = tid4 * 2;
    #pragma unroll
    for (int nt = 0; nt < 8; nt++) {
        int n = nt*8 + n0;
        *(float2*)&d_part[pb + (long)j0*64 + n]       = make_float2(c[nt][0], c[nt][1]);
        *(float2*)&d_part[pb + (long)(j0 + 8)*64 + n] = make_float2(c[nt][2], c[nt][3]);
    }
}

// ------------- reduce partials + bias, split (mu, logvar) -------------
__global__ void k_fin(const float* __restrict__ bfc, float* __restrict__ out) {
    int e = blockIdx.x * blockDim.x + threadIdx.x;
    if (e >= 8192) return;
    float s = 0.f;
    #pragma unroll 8
    for (int blk = 0; blk < NKB; blk++) s += d_part[(long)blk * 8192 + e];
    int j = e >> 6, b = e & 63;
    out[(j >> 6) * 4096 + b*64 + (j & 63)] = s + bfc[j];
}

extern "C" void kernel_launch(void* const* d_in, const int* in_sizes, int n_in,
                              void* d_out, int out_size) {
    const float* x0    = (const float*)d_in[0];
    const float* x1    = (const float*)d_in[1];
    const float* x2    = (const float*)d_in[2];
    const float* x3    = (const float*)d_in[3];
    const float* x4    = (const float*)d_in[4];
    const float* Wlin  = (const float*)d_in[5];
    const float* bias0 = (const float*)d_in[6];
    const float* w3j   = (const float*)d_in[7];
    const float* Wfc   = (const float*)d_in[8];
    const float* bfc   = (const float*)d_in[9];
    float* out = (float*)d_out;

    k_shim<<<1, 32>>>();                 // #1
    k_shim<<<1, 32>>>();                 // #2
    k_y<<<64, 256>>>(x0, x1, x2, x3, x4, Wlin, bias0);          // #3
    k_trip_all<<<dim3(NTRIP, 64), 256>>>(w3j);                  // #4 -> profiled
    k_bncol<<<DTOT/1024, 256>>>();
    k_bnred<<<NTRIP*32, 32>>>();
    k_gemm_mma<<<NKB, 256>>>(Wfc);
    k_fin<<<32, 256>>>(bfc, out);
}